// round 14
// baseline (speedup 1.0000x reference)
#include <cuda_runtime.h>
#include <cstdint>

// high_order_input: x[4,8,128,128] f32 -> out[4,8,210,16384] f32
// ht2: 45 pairs c_i*c_j (i<=j); ht3: 165 triples c_i*c_j*c_k (i<=j<=k), matching
// reference tpcm2/tpcm3 order (verified rel_err 3.9e-08 across R1-R12).
//
// R14 = R13 resubmitted after an infra-side container failure (kernel never ran).
// R12 (fully specialized term-major: 1 CTA = (plane, term), 6720 uniform CTAs,
// 16-row warp runs, compile-time row picks + shifts) with ONE change: plain
// write-back stores instead of __stcs. R7 and R12 both measured exactly
// 65.632us despite 2x different issue pressure -> external write-path floor.
// A/B test: does evict-first streaming hurt L2 writeback batching / DRAM page
// locality vs default write-back aging?

#define HWDIM 128
#define LPIX  (HWDIM * HWDIM)   // 16384
#define NTERM 210
#define FULLM 0xffffffffu

// constexpr decode of term t -> (i, j, k); k = -1 for order-2 terms.
// Enumeration: t2 = 0..44 (i-major, j>=i); t3 = 45..209 (i-major, j>=i, k>=j).
__host__ __device__ constexpr int dec3(int t, int sel)
{
    if (t < 45) {
        int rem = t, i = 0;
        while (rem >= 9 - i) { rem -= 9 - i; i++; }
        const int j = i + rem;
        return sel == 0 ? i : (sel == 1 ? j : -1);
    }
    int rem = t - 45, i = 0;
    for (;;) {
        const int c = (9 - i) * (10 - i) / 2;
        if (rem < c) break;
        rem -= c; i++;
    }
    int j = i;
    while (rem >= 9 - j) { rem -= 9 - j; j++; }
    const int k = j + rem;
    return sel == 0 ? i : (sel == 1 ? j : k);
}

__device__ __forceinline__ float4 zero4() { return make_float4(0.f, 0.f, 0.f, 0.f); }

__device__ __forceinline__ float4 ldg4(const float* p)
{
    return __ldg(reinterpret_cast<const float4*>(p));
}

// Compile-time horizontal shift of a warp-distributed row (lane L = cols 4L..4L+3).
// C=0 -> cols w-1 (zero pad), C=1 -> centered, C=2 -> cols w+1 (zero pad).
template <int C>
__device__ __forceinline__ float4 hshiftc(float4 v, int lane)
{
    if (C == 1) return v;
    if (C == 0) {
        float pw = __shfl_up_sync(FULLM, v.w, 1);
        return make_float4(lane == 0 ? 0.f : pw, v.x, v.y, v.z);
    }
    float nx = __shfl_down_sync(FULLM, v.x, 1);
    return make_float4(v.y, v.z, v.w, lane == 31 ? 0.f : nx);
}

template <int DR>
__device__ __forceinline__ float4 rpick(float4 rm, float4 rc, float4 rp)
{
    return (DR == 0) ? rm : (DR == 1) ? rc : rp;
}

template <int T>
__device__ __forceinline__ void run_term(const float* __restrict__ xp,
                                         float* __restrict__ op,
                                         int lane, int rowbase)
{
    constexpr int I = dec3(T, 0);
    constexpr int J = dec3(T, 1);
    constexpr int K = dec3(T, 2);
    constexpr bool TRIPLE = (K >= 0);
    constexpr int DI = I / 3, CI = I % 3;
    constexpr int DJ = J / 3, CJ = J % 3;
    constexpr int DK = TRIPLE ? K / 3 : 1;
    constexpr int CK = TRIPLE ? K % 3 : 1;

    const int colb = lane * 4;

    // Rolling 3-row window (zero-padded at plane edges).
    float4 rm = (rowbase > 0) ? ldg4(xp + (rowbase - 1) * HWDIM + colb) : zero4();
    float4 rc = ldg4(xp + rowbase * HWDIM + colb);

    #pragma unroll 2
    for (int it = 0; it < 16; it++) {
        const int h = rowbase + it;
        float4 rp = (h < HWDIM - 1) ? ldg4(xp + (h + 1) * HWDIM + colb) : zero4();

        float4 vi = hshiftc<CI>(rpick<DI>(rm, rc, rp), lane);
        float4 vj = hshiftc<CJ>(rpick<DJ>(rm, rc, rp), lane);

        float4 r;
        r.x = vi.x * vj.x;
        r.y = vi.y * vj.y;
        r.z = vi.z * vj.z;
        r.w = vi.w * vj.w;

        if (TRIPLE) {
            float4 vk = hshiftc<CK>(rpick<DK>(rm, rc, rp), lane);
            r.x *= vk.x;
            r.y *= vk.y;
            r.z *= vk.z;
            r.w *= vk.w;
        }

        // A/B vs R12: default write-back store (was __stcs evict-first).
        *reinterpret_cast<float4*>(op + h * HWDIM + colb) = r;
        rm = rc;
        rc = rp;
    }
}

__global__ __launch_bounds__(256, 6)
void high_order_term_kernel(const float* __restrict__ x, float* __restrict__ out)
{
    const int cta = blockIdx.x;           // plane-major: concurrent CTAs cluster
    const int p   = cta / NTERM;          // writes into a compact output region
    const int t   = cta - p * NTERM;

    const int lane = threadIdx.x & 31;
    const int warp = threadIdx.x >> 5;
    const int rowbase = warp * 16;        // 8 warps x 16 rows = full plane

    const float* __restrict__ xp = x + (size_t)p * LPIX;
    float* __restrict__ op = out + ((size_t)p * NTERM + t) * LPIX;

#define HO_C1(t_) case (t_): run_term<(t_)>(xp, op, lane, rowbase); break;
#define HO_C5(t_)  HO_C1(t_) HO_C1((t_)+1) HO_C1((t_)+2) HO_C1((t_)+3) HO_C1((t_)+4)
#define HO_C25(t_) HO_C5(t_) HO_C5((t_)+5) HO_C5((t_)+10) HO_C5((t_)+15) HO_C5((t_)+20)

    switch (t) {
        HO_C25(0)   HO_C25(25)  HO_C25(50)  HO_C25(75)
        HO_C25(100) HO_C25(125) HO_C25(150) HO_C25(175)
        HO_C5(200)  HO_C5(205)
    }

#undef HO_C25
#undef HO_C5
#undef HO_C1
}

extern "C" void kernel_launch(void* const* d_in, const int* in_sizes, int n_in,
                              void* d_out, int out_size)
{
    const float* x = (const float*)d_in[0];
    float* out = (float*)d_out;
    // tpcm2 (d_in[1]) / tpcm3 (d_in[2]) are compile-time constants for K=3; hardcoded.
    (void)in_sizes; (void)n_in; (void)out_size;

    const int grid = 32 * NTERM;   // 6720 uniform CTAs, plane-major order
    const int block = 256;         // 8 warps x 16 rows
    high_order_term_kernel<<<grid, block>>>(x, out);
}